// round 5
// baseline (speedup 1.0000x reference)
#include <cuda_runtime.h>
#include <cuda_bf16.h>
#include <cstdint>

// I=16, O=8, J=4, B=16 -> n_in=1024, n_out=256, K=81 projectors.
// Each output quad out[b, ij_r*4+ch, 4*gc..+3] is a masked sum of 4 gathered
// input quads. In quad (float4) units, with u = global thread id:
//   base = b<<18 | i_r<<15 | j_r<<11 | ch<<8 | i_c<<5 | j_c<<1
// which is a 4-shift bit-permutation of u:
//   base = ((u&7)<<1) + ((u&0xF8)<<2) + ((u&0x700)<<3) + ((u&0x3F800)<<4)
// and the four source quads sit at CONSTANT offsets from base:
//   B = base + 0,  C = base + 1025,  D = base + 16400,  center = base + 17425
// (center always added; C iff i_r==i_c; D iff j_r==j_c; B iff both).
// Max index: base_max + 17425 = 2^22 - 1 = last element -> always in bounds,
// so all four loads are issued unconditionally and masked via packed FMA.

__device__ __forceinline__ unsigned long long fma2(unsigned long long a,
                                                   unsigned long long b,
                                                   unsigned long long c)
{
    unsigned long long d;
    asm("fma.rn.f32x2 %0, %1, %2, %3;" : "=l"(d) : "l"(a), "l"(b), "l"(c));
    return d;
}

__device__ __forceinline__ unsigned long long pk(float a, float b)
{
    unsigned long long r;
    asm("mov.b64 %0, {%1, %2};" : "=l"(r) : "f"(a), "f"(b));
    return r;
}

__global__ __launch_bounds__(256, 8)
void pool2d_density_kernel(const float4* __restrict__ xq, float4* __restrict__ oq)
{
    const int u = blockIdx.x * 256 + threadIdx.x;      // 0..262143 = output quad

    // 4-shift bit permutation -> base quad index (see header comment)
    const int base = ((u & 7)       << 1)
                   + ((u & 0xF8)    << 2)
                   + ((u & 0x700)   << 3)
                   + ((u & 0x3F800) << 4);

    const float4* p = xq + base;

    // four independent LDG.128 with constant immediate offsets, no gating
    const float4 vB = __ldg(p);             // + 0
    const float4 vC = __ldg(p + 1025);      // C group
    const float4 vD = __ldg(p + 16400);     // D group
    const float4 v0 = __ldg(p + 17425);     // center (always added)

    // match predicates from bit fields of u
    const bool im = ((u >> 11) & 7) == ((u >> 3) & 7);   // i_r == i_c
    const bool jm = ((u >> 8)  & 7) == (u & 7);          // j_r == j_c

    const unsigned long long ONE2 = 0x3F8000003F800000ULL;
    const unsigned long long mi = im ? ONE2 : 0ULL;
    const unsigned long long mj = jm ? ONE2 : 0ULL;
    const unsigned long long mb = (im & jm) ? ONE2 : 0ULL;

    // packed f32x2 accumulate: acc = v0 + mi*vC + mj*vD + mb*vB
    unsigned long long lo = pk(v0.x, v0.y);
    unsigned long long hi = pk(v0.z, v0.w);
    lo = fma2(mi, pk(vC.x, vC.y), lo);
    hi = fma2(mi, pk(vC.z, vC.w), hi);
    lo = fma2(mj, pk(vD.x, vD.y), lo);
    hi = fma2(mj, pk(vD.z, vD.w), hi);
    lo = fma2(mb, pk(vB.x, vB.y), lo);
    hi = fma2(mb, pk(vB.z, vB.w), hi);

    // output quad linear index == u (fully coalesced 128B stores per warp)
    ulonglong2 r; r.x = lo; r.y = hi;
    ((ulonglong2*)oq)[u] = r;
}

extern "C" void kernel_launch(void* const* d_in, const int* in_sizes, int n_in,
                              void* d_out, int out_size)
{
    const float4* x = (const float4*)d_in[0];   // (16, 1024, 1024) fp32 as quads
    float4* out = (float4*)d_out;               // (16, 256, 256) fp32 as quads

    // 262144 output quads, 1 per thread: 1024 blocks x 256 threads
    pool2d_density_kernel<<<1024, 256>>>(x, out);
}